// round 11
// baseline (speedup 1.0000x reference)
#include <cuda_runtime.h>
#include <math.h>

namespace {
constexpr int NDIM   = 4;
constexpr int KW     = 32;      // N_WIDTH total
constexpr int KH     = 16;      // widths per CTA (k split across 2 CTAs)
constexpr int NN     = 193;     // N_NODES
constexpr int NELEM  = 64;
constexpr int TILE_I = 224;
constexpr int THREADS = 768;
constexpr int NWARP  = THREADS / 32;          // 24
constexpr int PPW    = 5;                     // pairs per warp (24*5*2=240 >= 224)

constexpr int KSL    = 4;                     // k per build slice
constexpr int NSLICE = KH / KSL;              // 4
constexpr int WIN_ROW = NN * NDIM;            // 772 floats per k
constexpr int RAW_IN_SL  = KSL * WIN_ROW;     // 3088 floats
constexpr int RAW_OUT_SL = KSL * NN;          // 772 floats

constexpr int NC_IN_H  = NELEM * 4 * KH;      // 4096 float4 (inner, this half)
constexpr int NC_OUT_H = NELEM * KH;          // 1024 float4 (outer, this half)

// smem layout in float4 units
constexpr int OFF_CIN  = 0;                      // [(e*4+j)*16 + kk]
constexpr int OFF_COUT = OFF_CIN  + NC_IN_H;     // [e*16 + kk]
constexpr int OFF_XR   = OFF_COUT + NC_OUT_H;    // float4 [TILE_I]
constexpr int OFF_E4   = OFF_XR   + TILE_I;      // int4   [TILE_I]
constexpr int OFF_RAW  = OFF_E4   + TILE_I;      // raw slice 3860 fl = 965 f4
constexpr int SMEM_V4  = OFF_RAW  + (RAW_IN_SL + RAW_OUT_SL + 3) / 4;  // 6533
constexpr int SMEM_BYTES = SMEM_V4 * 16;         // 104528 B -> 2 CTAs/SM

constexpr float THIRD = 0.33333334f;             // RN(1/3)

static_assert(SMEM_BYTES * 2 <= 228 * 1024, "2 CTAs must fit");
}

// exact floor(div_rn(xs,3)) for xs in [0,192] without FP division
__device__ __forceinline__ float floor_div3(float xs) {
    float fe = floorf(xs * THIRD);
    float r  = fmaf(-3.0f, fe, xs);
    fe += (r >= 3.0f) ? 1.0f : 0.0f;
    fe -= (r < 0.0f)  ? 1.0f : 0.0f;
    return fe;
}

__global__ __launch_bounds__(THREADS, 2)
void kann_kernel(const float* __restrict__ x,
                 const float* __restrict__ Win,
                 const float* __restrict__ Wout,
                 float* __restrict__ out,
                 int I)
{
    extern __shared__ float4 smv[];
    float4* sCin  = smv + OFF_CIN;
    float4* sCout = smv + OFF_COUT;
    float4* sXR   = smv + OFF_XR;
    int4*   sE4   = (int4*)(smv + OFF_E4);
    float*  sXRf  = (float*)sXR;
    int*    sEf   = (int*)sE4;
    float*  sRaw  = (float*)(smv + OFF_RAW);       // Win slice [3088]
    float*  sRawO = sRaw + RAW_IN_SL;              // Wout slice [772]

    const int tid    = threadIdx.x;
    const int i_base = blockIdx.x * TILE_I;
    const int k0     = blockIdx.y * KH;

    // ---- phase 1: per-(sample,dim) transform (x-only) ----
    for (int t = tid; t < TILE_I * NDIM; t += THREADS) {
        const int li = t >> 2;
        const int j  = t & 3;
        const int i  = i_base + li;
        float xr = 0.f;
        int   ei = 0;
        if (i < I) {
            float v  = x[i * NDIM + j];
            float xs = 192.0f * (v + 1.0f) / 2.0f;   // exact /2
            float fe = floor_div3(xs);
            fe = fminf(fmaxf(fe, 0.0f), 63.0f);
            float nl = 3.0f * fe;                     // exact
            xr = fmaf(2.0f * (xs - nl), THIRD, -1.0f);
            ei = (int)fe;
        }
        sXRf[t] = xr;
        sEf[t]  = ei;
    }

    // ---- build this half's coeff tables, 4 k-slices of 4 ----
    const float g00 = -0.0625f, g01 =  0.0625f, g02 =  0.5625f, g03 = -0.5625f;
    const float g10 =  0.5625f, g11 = -1.6875f, g12 = -0.5625f, g13 =  1.6875f;
    const float g20 =  0.5625f, g21 =  1.6875f, g22 = -0.5625f, g23 = -1.6875f;
    const float g30 = -0.0625f, g31 = -0.0625f, g32 =  0.5625f, g33 =  0.5625f;

    #pragma unroll
    for (int sl = 0; sl < NSLICE; sl++) {
        __syncthreads();                       // protect reused raw buffer
        const float* gin = Win + (k0 + sl * KSL) * WIN_ROW;
        #pragma unroll
        for (int it = 0; it < (RAW_IN_SL + THREADS - 1) / THREADS; it++) {
            int t = it * THREADS + tid;
            if (t < RAW_IN_SL) sRaw[t] = gin[t];
        }
        {
            int t = tid;
            if (t < RAW_OUT_SL) sRawO[t] = Wout[(k0 + sl * KSL) * NN + t];
        }
        __syncthreads();

        // inner coeffs: 1024 items (e,j,kk4)
        #pragma unroll
        for (int it = 0; it < 2; it++) {
            int idx = it * THREADS + tid;
            if (idx < NELEM * 4 * KSL) {
                int kk = idx & 3;
                int ej = idx >> 2;             // e*4 + j
                int j  = ej & 3;
                int e  = ej >> 2;
                const float* w = sRaw + kk * WIN_ROW + (3 * e) * NDIM + j;
                float w0 = w[0], w1 = w[NDIM], w2 = w[2 * NDIM], w3 = w[3 * NDIM];
                float4 a;
                a.x = w0 * g00 + w1 * g10 + w2 * g20 + w3 * g30;
                a.y = w0 * g01 + w1 * g11 + w2 * g21 + w3 * g31;
                a.z = w0 * g02 + w1 * g12 + w2 * g22 + w3 * g32;
                a.w = w0 * g03 + w1 * g13 + w2 * g23 + w3 * g33;
                sCin[ej * KH + sl * KSL + kk] = a;
            }
        }
        // outer coeffs: 256 items (e,kk4)
        if (tid < NELEM * KSL) {
            int kk = tid & 3;
            int e  = tid >> 2;
            const float* w = sRawO + kk * NN + 3 * e;
            float w0 = w[0], w1 = w[1], w2 = w[2], w3 = w[3];
            float4 b;
            b.x = w0 * g00 + w1 * g10 + w2 * g20 + w3 * g30;
            b.y = w0 * g01 + w1 * g11 + w2 * g21 + w3 * g31;
            b.z = w0 * g02 + w1 * g12 + w2 * g22 + w3 * g32;
            b.w = w0 * g03 + w1 * g13 + w2 * g23 + w3 * g33;
            sCout[e * KH + sl * KSL + kk] = b;
        }
    }
    __syncthreads();

    // ---- phase 2: warp = 2 samples (16-lane halves), lane&15 = width kk ----
    const int warp = tid >> 5;
    const int lane = tid & 31;
    const int sw   = lane >> 4;                 // sample within pair
    const int kk   = lane & 15;
    const int IK   = I * KW;

    #pragma unroll
    for (int q = 0; q < PPW; q++) {
        const int pair   = warp * PPW + q;      // 0..119
        const int li_raw = pair * 2 + sw;       // 0..239
        const int li     = li_raw < TILE_I ? li_raw : TILE_I - 1;
        const int i      = i_base + li;
        const bool valid = (li_raw < TILE_I) && (i < I);

        const float4 xr4 = sXR[li];
        const int4   e4  = sE4[li];

        float tv = 0.f, dtv = 0.f, ddtv = 0.f;
        #pragma unroll
        for (int j = 0; j < 4; j++) {
            float xr = (j == 0) ? xr4.x : (j == 1) ? xr4.y : (j == 2) ? xr4.z : xr4.w;
            int   e  = (j == 0) ? e4.x  : (j == 1) ? e4.y  : (j == 2) ? e4.z  : e4.w;
            float4 a = sCin[((e << 2) | j) * KH + kk];     // LDS.128
            float h1 = fmaf(a.w, xr, a.z);
            float h2 = fmaf(h1,  xr, a.y);
            float h3 = fmaf(h2,  xr, a.x);
            float q2 = fmaf(a.w, xr, h1);
            float q3 = fmaf(q2,  xr, h2);
            float r  = fmaf(a.w, xr, q2);
            tv   += h3;
            dtv  += q3;
            ddtv += r;
        }
        dtv  *= 64.0f;    // p'/delta,      delta = 1/64 exactly
        ddtv *= 8192.0f;  // 2*r/delta^2

        // outer layer on t, domain [-3,3]
        float xs = 192.0f * (tv + 3.0f) / 6.0f;
        float fe = floor_div3(xs);
        fe = fminf(fmaxf(fe, 0.0f), 63.0f);
        float nl = 3.0f * fe;
        float xr = fmaf(2.0f * (xs - nl), THIRD, -1.0f);

        float4 b = sCout[(int)fe * KH + kk];               // LDS.128
        float y = fmaf(fmaf(fmaf(b.w, xr, b.z), xr, b.y), xr, b.x);

        if (valid) {
            int o = i * KW + k0 + kk;
            out[o]          = y;
            out[o + IK]     = tv;
            out[o + 2 * IK] = dtv;
            out[o + 3 * IK] = ddtv;
        }
    }
}

extern "C" void kernel_launch(void* const* d_in, const int* in_sizes, int n_in,
                              void* d_out, int out_size)
{
    const float* x    = (const float*)d_in[0];
    const float* Win  = (const float*)d_in[1];
    const float* Wout = (const float*)d_in[2];
    float* out = (float*)d_out;

    int I = in_sizes[0] / NDIM;                       // 32768
    dim3 grid((I + TILE_I - 1) / TILE_I, 2);          // 147 x 2 = 294 CTAs

    cudaFuncSetAttribute(kann_kernel,
                         cudaFuncAttributeMaxDynamicSharedMemorySize, SMEM_BYTES);
    kann_kernel<<<grid, THREADS, SMEM_BYTES>>>(x, Win, Wout, out, I);
}